// round 5
// baseline (speedup 1.0000x reference)
#include <cuda_runtime.h>
#include <mma.h>
#include <math.h>

using namespace nvcuda;

#define T 2048
#define DIM 768
#define NH 12
#define HD 64

// Scratch (allocation-free: __device__ globals)
__device__ float g_qkv[3][T * DIM];   // raw q,k,v projections, [t][768] layout
__device__ float g_q[T * DIM];        // [h][t][64]
__device__ float g_k[T * DIM];        // [h][t][64]
__device__ float g_v[T * DIM];        // [h][t][64]
__device__ float g_att[T * DIM];      // attention output, [t][768] layout

// ---------------------------------------------------------------------------
// TF32 wmma GEMM-NT: C[m][n] = sum_k A[m*DIM+k] * B[n*DIM+k]
// Block tile 128x64, BK=32, double-buffered smem, 8 warps (4x2),
// warp tile 32x32 (2x2 m16n16k8 frags).
// ---------------------------------------------------------------------------
#define BM 128
#define BN 64
#define BK 32

__device__ __forceinline__ float tf32c(float x) { return wmma::__float_to_tf32(x); }

__device__ __forceinline__ void gemm_tile_tf32(const float* __restrict__ A,
                                               const float* __restrict__ B,
                                               float* __restrict__ C) {
    __shared__ float As[2][BM * BK];
    __shared__ float Bs[2][BN * BK];
    const int tid = threadIdx.x;
    const int wid = tid >> 5;
    const int m0 = blockIdx.y * BM, n0 = blockIdx.x * BN;
    const int warp_m = wid >> 1;   // 0..3
    const int warp_n = wid & 1;    // 0..1
    const int r0 = tid >> 3;       // 0..31
    const int c4 = (tid & 7) * 4;  // 0..28

    float4 pa[4], pb[2];

    wmma::fragment<wmma::accumulator, 16, 16, 8, float> acc[2][2];
#pragma unroll
    for (int i = 0; i < 2; i++)
#pragma unroll
        for (int j = 0; j < 2; j++) wmma::fill_fragment(acc[i][j], 0.0f);

    auto load_regs = [&](int k0) {
#pragma unroll
        for (int i = 0; i < 4; i++)
            pa[i] = *(const float4*)&A[(m0 + r0 + i * 32) * DIM + k0 + c4];
#pragma unroll
        for (int i = 0; i < 2; i++)
            pb[i] = *(const float4*)&B[(n0 + r0 + i * 32) * DIM + k0 + c4];
    };
    auto store_smem = [&](int buf) {
#pragma unroll
        for (int i = 0; i < 4; i++) {
            float* p = &As[buf][(r0 + i * 32) * BK + c4];
            p[0] = tf32c(pa[i].x); p[1] = tf32c(pa[i].y);
            p[2] = tf32c(pa[i].z); p[3] = tf32c(pa[i].w);
        }
#pragma unroll
        for (int i = 0; i < 2; i++) {
            float* p = &Bs[buf][(r0 + i * 32) * BK + c4];
            p[0] = tf32c(pb[i].x); p[1] = tf32c(pb[i].y);
            p[2] = tf32c(pb[i].z); p[3] = tf32c(pb[i].w);
        }
    };

    const int NSTEP = DIM / BK;  // 24
    load_regs(0);
    store_smem(0);
    load_regs(BK);
    __syncthreads();

    for (int s = 0; s < NSTEP; s++) {
        const int buf = s & 1;
#pragma unroll
        for (int kk = 0; kk < BK; kk += 8) {
            wmma::fragment<wmma::matrix_a, 16, 16, 8, wmma::precision::tf32, wmma::row_major> af[2];
            wmma::fragment<wmma::matrix_b, 16, 16, 8, wmma::precision::tf32, wmma::col_major> bf[2];
#pragma unroll
            for (int i = 0; i < 2; i++)
                wmma::load_matrix_sync(af[i], &As[buf][(warp_m * 32 + i * 16) * BK + kk], BK);
#pragma unroll
            for (int j = 0; j < 2; j++)
                wmma::load_matrix_sync(bf[j], &Bs[buf][(warp_n * 32 + j * 16) * BK + kk], BK);
#pragma unroll
            for (int i = 0; i < 2; i++)
#pragma unroll
                for (int j = 0; j < 2; j++)
                    wmma::mma_sync(acc[i][j], af[i], bf[j], acc[i][j]);
        }
        if (s + 1 < NSTEP) {
            __syncthreads();
            store_smem((s + 1) & 1);
            if (s + 2 < NSTEP) load_regs((s + 2) * BK);
            __syncthreads();
        }
    }
#pragma unroll
    for (int i = 0; i < 2; i++)
#pragma unroll
        for (int j = 0; j < 2; j++)
            wmma::store_matrix_sync(
                &C[(m0 + warp_m * 32 + i * 16) * DIM + n0 + warp_n * 32 + j * 16],
                acc[i][j], DIM, wmma::mem_row_major);
}

__global__ void gemm_qkv_kernel(const float* __restrict__ x,
                                const float* __restrict__ Wq,
                                const float* __restrict__ Wk,
                                const float* __restrict__ Wv) {
    const int z = blockIdx.z;
    const float* B = (z == 0) ? Wq : (z == 1) ? Wk : Wv;
    gemm_tile_tf32(x, B, &g_qkv[z][0]);
}

__global__ void gemm_out_kernel(const float* __restrict__ Wp,
                                float* __restrict__ out) {
    gemm_tile_tf32(g_att, Wp, out);
}

// ---------------------------------------------------------------------------
// Epilogue: v = (1-l)*v + l*vi ; q,k = rope(rmsnorm(q|k)); relayout to [h][t][64]
// One warp per (t, head).
// ---------------------------------------------------------------------------
__global__ void qkv_epilogue_kernel(const float* __restrict__ vi,
                                    const float* __restrict__ lamb) {
    const int w = (blockIdx.x * blockDim.x + threadIdx.x) >> 5;
    const int lane = threadIdx.x & 31;
    if (w >= T * NH) return;
    const int t = w / NH;
    const int h = w % NH;

    const int src = t * DIM + h * HD;
    const int dst = (h * T + t) * HD;

    const float invf = (float)pow(10000.0, -(double)lane / 32.0);
    const float ang = (float)t * invf;
    float sa, ca;
    sincosf(ang, &sa, &ca);

    const float eps = 1.1920929e-07f;

    {
        float a = g_qkv[0][src + lane];
        float b = g_qkv[0][src + 32 + lane];
        float ss = a * a + b * b;
#pragma unroll
        for (int m = 16; m >= 1; m >>= 1) ss += __shfl_xor_sync(0xffffffffu, ss, m);
        float r = rsqrtf(ss * (1.0f / 64.0f) + eps);
        a *= r; b *= r;
        g_q[dst + lane]      = a * ca + b * sa;
        g_q[dst + 32 + lane] = -a * sa + b * ca;
    }
    {
        float a = g_qkv[1][src + lane];
        float b = g_qkv[1][src + 32 + lane];
        float ss = a * a + b * b;
#pragma unroll
        for (int m = 16; m >= 1; m >>= 1) ss += __shfl_xor_sync(0xffffffffu, ss, m);
        float r = rsqrtf(ss * (1.0f / 64.0f) + eps);
        a *= r; b *= r;
        g_k[dst + lane]      = a * ca + b * sa;
        g_k[dst + 32 + lane] = -a * sa + b * ca;
    }
    {
        const float l = lamb[0];
        float va = g_qkv[2][src + lane];
        float vb = g_qkv[2][src + 32 + lane];
        float ia = vi[src + lane];
        float ib = vi[src + 32 + lane];
        g_v[dst + lane]      = (1.0f - l) * va + l * ia;
        g_v[dst + 32 + lane] = (1.0f - l) * vb + l * ib;
    }
}

// ---------------------------------------------------------------------------
// Flash attention, causal, TF32 tensor cores, FIXED-MAX softmax.
// After rms_norm, |q|=|k|=8 exactly, so scores = q.k/8 are in [-8, 8]:
// exp() cannot overflow, so we skip the online max/rescale entirely.
// P = exp(s), l = sum P accumulated per row; O accumulates in register
// fragments across the whole kt loop; normalized by 1/l once at the end.
// Block per (q-tile of 64, head). 256 threads = 8 warps (4m x 2n),
// each warp owns 16 rows x 32 cols.
// ---------------------------------------------------------------------------
__global__ void attn_kernel() {
    extern __shared__ float sm[];
    float* Qs = sm;              // 64x64 (tf32)
    float* Ks = Qs + 4096;       // 64x64 (tf32)
    float* Vs = Ks + 4096;       // 64x64 (tf32)
    float* Ss = Vs + 4096;       // 64x64 scores -> P (tf32), then O at the end
    __shared__ float lrow[64];

    const int qt = blockIdx.x;
    const int h = blockIdx.y;
    const int tid = threadIdx.x;
    const int wid = tid >> 5;
    const int warp_m = wid >> 1;  // 0..3
    const int warp_n = wid & 1;   // 0..1
    const int q0 = qt * 64;

    const float* qh = g_q + h * T * HD;
    const float* kh = g_k + h * T * HD;
    const float* vh = g_v + h * T * HD;

    // load Q tile (tf32)
    for (int v = tid; v < 64 * 16; v += 256) {
        int r = v >> 4, c4 = (v & 15) * 4;
        float4 q = *(const float4*)&qh[(q0 + r) * HD + c4];
        Qs[r * 64 + c4 + 0] = tf32c(q.x);
        Qs[r * 64 + c4 + 1] = tf32c(q.y);
        Qs[r * 64 + c4 + 2] = tf32c(q.z);
        Qs[r * 64 + c4 + 3] = tf32c(q.w);
    }
    if (tid < 64) lrow[tid] = 0.0f;

    // O accumulator fragments: 16 rows x 32 cols per warp, live whole loop
    wmma::fragment<wmma::accumulator, 16, 16, 8, float> oacc[2];
#pragma unroll
    for (int j = 0; j < 2; j++) wmma::fill_fragment(oacc[j], 0.0f);

    const int row = tid >> 2;     // 0..63 softmax row
    const int cg = tid & 3;       // col group, 16 cols each

    for (int kt = 0; kt <= qt; kt++) {
        __syncthreads();  // previous iter's PV readers of Ks/Vs/Ss done
        for (int v = tid; v < 64 * 16; v += 256) {
            int r = v >> 4, c4 = (v & 15) * 4;
            float4 k = *(const float4*)&kh[(kt * 64 + r) * HD + c4];
            float4 vv = *(const float4*)&vh[(kt * 64 + r) * HD + c4];
            Ks[r * 64 + c4 + 0] = tf32c(k.x);
            Ks[r * 64 + c4 + 1] = tf32c(k.y);
            Ks[r * 64 + c4 + 2] = tf32c(k.z);
            Ks[r * 64 + c4 + 3] = tf32c(k.w);
            Vs[r * 64 + c4 + 0] = tf32c(vv.x);
            Vs[r * 64 + c4 + 1] = tf32c(vv.y);
            Vs[r * 64 + c4 + 2] = tf32c(vv.z);
            Vs[r * 64 + c4 + 3] = tf32c(vv.w);
        }
        __syncthreads();

        // S = Q . K^T
        {
            wmma::fragment<wmma::accumulator, 16, 16, 8, float> sacc[2];
#pragma unroll
            for (int j = 0; j < 2; j++) wmma::fill_fragment(sacc[j], 0.0f);
#pragma unroll
            for (int kk = 0; kk < 64; kk += 8) {
                wmma::fragment<wmma::matrix_a, 16, 16, 8, wmma::precision::tf32, wmma::row_major> af;
                wmma::fragment<wmma::matrix_b, 16, 16, 8, wmma::precision::tf32, wmma::col_major> bf[2];
                wmma::load_matrix_sync(af, &Qs[(warp_m * 16) * 64 + kk], 64);
#pragma unroll
                for (int j = 0; j < 2; j++)
                    wmma::load_matrix_sync(bf[j], &Ks[(warp_n * 32 + j * 16) * 64 + kk], 64);
#pragma unroll
                for (int j = 0; j < 2; j++)
                    wmma::mma_sync(sacc[j], af, bf[j], sacc[j]);
            }
#pragma unroll
            for (int j = 0; j < 2; j++)
                wmma::store_matrix_sync(&Ss[(warp_m * 16) * 64 + warp_n * 32 + j * 16],
                                        sacc[j], 64, wmma::mem_row_major);
        }
        __syncthreads();

        // P = exp(S*scale) with causal mask; accumulate row sums (no max needed)
        {
            const bool diag = (kt == qt);
            float rs = 0.0f;
#pragma unroll
            for (int c = 0; c < 16; c++) {
                int cc = cg * 16 + c;
                float p;
                if (diag && cc > row) {
                    p = 0.0f;
                } else {
                    p = __expf(Ss[row * 64 + cc] * 0.125f);
                }
                rs += p;
                Ss[row * 64 + cc] = tf32c(p);
            }
            rs += __shfl_xor_sync(0xffffffffu, rs, 1);
            rs += __shfl_xor_sync(0xffffffffu, rs, 2);
            if (cg == 0) lrow[row] += rs;
        }
        __syncthreads();

        // O += P . V (accumulate in registers)
#pragma unroll
        for (int kk = 0; kk < 64; kk += 8) {
            wmma::fragment<wmma::matrix_a, 16, 16, 8, wmma::precision::tf32, wmma::row_major> af;
            wmma::fragment<wmma::matrix_b, 16, 16, 8, wmma::precision::tf32, wmma::row_major> bf[2];
            wmma::load_matrix_sync(af, &Ss[(warp_m * 16) * 64 + kk], 64);
#pragma unroll
            for (int j = 0; j < 2; j++)
                wmma::load_matrix_sync(bf[j], &Vs[kk * 64 + warp_n * 32 + j * 16], 64);
#pragma unroll
            for (int j = 0; j < 2; j++)
                wmma::mma_sync(oacc[j], af, bf[j], oacc[j]);
        }
    }

    // dump O fragments once, normalize, write out in [t][768] layout
    __syncthreads();
#pragma unroll
    for (int j = 0; j < 2; j++)
        wmma::store_matrix_sync(&Ss[(warp_m * 16) * 64 + warp_n * 32 + j * 16],
                                oacc[j], 64, wmma::mem_row_major);
    __syncthreads();
    {
        float inv = 1.0f / lrow[row];
#pragma unroll
        for (int c = 0; c < 16; c++)
            g_att[(q0 + row) * DIM + h * HD + cg * 16 + c] = Ss[row * 64 + cg * 16 + c] * inv;
    }
}

// ---------------------------------------------------------------------------
extern "C" void kernel_launch(void* const* d_in, const int* in_sizes, int n_in,
                              void* d_out, int out_size) {
    const float* x    = (const float*)d_in[0];
    const float* vi   = (const float*)d_in[1];
    const float* Wq   = (const float*)d_in[2];
    const float* Wk   = (const float*)d_in[3];
    const float* Wv   = (const float*)d_in[4];
    const float* Wp   = (const float*)d_in[5];
    const float* lamb = (const float*)d_in[6];
    float* out = (float*)d_out;

    static bool attr_set = false;
    if (!attr_set) {
        cudaFuncSetAttribute(attn_kernel,
                             cudaFuncAttributeMaxDynamicSharedMemorySize,
                             4 * 4096 * sizeof(float));
        attr_set = true;
    }

    dim3 gqkv(DIM / BN, T / BM, 3);
    gemm_qkv_kernel<<<gqkv, 256>>>(x, Wq, Wk, Wv);

    qkv_epilogue_kernel<<<(T * NH * 32) / 256, 256>>>(vi, lamb);

    dim3 gattn(T / 64, NH, 1);
    attn_kernel<<<gattn, 256, 4 * 4096 * sizeof(float)>>>();

    dim3 gout(DIM / BN, T / BM, 1);
    gemm_out_kernel<<<gout, 256>>>(Wp, out);
}

// round 7
// speedup vs baseline: 1.2238x; 1.2238x over previous
#include <cuda_runtime.h>
#include <mma.h>
#include <math.h>

using namespace nvcuda;

#define T 2048
#define DIM 768
#define NH 12
#define HD 64

// Scratch (allocation-free: __device__ globals)
__device__ float g_qkv[3][T * DIM];   // raw q,k,v projections, [t][768] layout
__device__ float g_q[T * DIM];        // [h][t][64]
__device__ float g_k[T * DIM];        // [h][t][64]
__device__ float g_v[T * DIM];        // [h][t][64]
__device__ float g_att[T * DIM];      // attention output, [t][768] layout

__device__ __forceinline__ float tf32c(float x) { return wmma::__float_to_tf32(x); }

// ---------------------------------------------------------------------------
// TF32 wmma GEMM-NT (Round-2 proven version): C[m][n] = sum_k A[m*DIM+k]*B[n*DIM+k]
// Block tile 128x64, 8 warps (4x2), warp tile 32x32 (2x2 m16n16k8), BK=16.
// ---------------------------------------------------------------------------
#define BM 128
#define BN 64
#define BK 16

__device__ __forceinline__ void gemm_tile_tf32(const float* __restrict__ A,
                                               const float* __restrict__ B,
                                               float* __restrict__ C) {
    __shared__ float As[BM][BK];   // [m][k]
    __shared__ float Bs[BN][BK];   // [n][k]
    const int tid = threadIdx.x;
    const int wid = tid >> 5;
    const int m0 = blockIdx.y * BM, n0 = blockIdx.x * BN;
    const int warp_m = wid >> 1;   // 0..3
    const int warp_n = wid & 1;    // 0..1

    wmma::fragment<wmma::accumulator, 16, 16, 8, float> acc[2][2];
#pragma unroll
    for (int i = 0; i < 2; i++)
#pragma unroll
        for (int j = 0; j < 2; j++) wmma::fill_fragment(acc[i][j], 0.0f);

    for (int k0 = 0; k0 < DIM; k0 += BK) {
        __syncthreads();
#pragma unroll
        for (int v = tid; v < BM * BK / 4; v += 256) {
            int r = v >> 2, c4 = (v & 3) * 4;
            float4 a = *(const float4*)&A[(m0 + r) * DIM + k0 + c4];
            As[r][c4 + 0] = tf32c(a.x);
            As[r][c4 + 1] = tf32c(a.y);
            As[r][c4 + 2] = tf32c(a.z);
            As[r][c4 + 3] = tf32c(a.w);
        }
        {
            int v = tid;  // BN*BK/4 == 256
            int r = v >> 2, c4 = (v & 3) * 4;
            float4 b = *(const float4*)&B[(n0 + r) * DIM + k0 + c4];
            Bs[r][c4 + 0] = tf32c(b.x);
            Bs[r][c4 + 1] = tf32c(b.y);
            Bs[r][c4 + 2] = tf32c(b.z);
            Bs[r][c4 + 3] = tf32c(b.w);
        }
        __syncthreads();
#pragma unroll
        for (int kk = 0; kk < BK; kk += 8) {
            wmma::fragment<wmma::matrix_a, 16, 16, 8, wmma::precision::tf32, wmma::row_major> af[2];
            wmma::fragment<wmma::matrix_b, 16, 16, 8, wmma::precision::tf32, wmma::col_major> bf[2];
#pragma unroll
            for (int i = 0; i < 2; i++)
                wmma::load_matrix_sync(af[i], &As[warp_m * 32 + i * 16][kk], BK);
#pragma unroll
            for (int j = 0; j < 2; j++)
                wmma::load_matrix_sync(bf[j], &Bs[warp_n * 32 + j * 16][kk], BK);
#pragma unroll
            for (int i = 0; i < 2; i++)
#pragma unroll
                for (int j = 0; j < 2; j++)
                    wmma::mma_sync(acc[i][j], af[i], bf[j], acc[i][j]);
        }
    }
#pragma unroll
    for (int i = 0; i < 2; i++)
#pragma unroll
        for (int j = 0; j < 2; j++)
            wmma::store_matrix_sync(
                &C[(m0 + warp_m * 32 + i * 16) * DIM + n0 + warp_n * 32 + j * 16],
                acc[i][j], DIM, wmma::mem_row_major);
}

__global__ void gemm_qkv_kernel(const float* __restrict__ x,
                                const float* __restrict__ Wq,
                                const float* __restrict__ Wk,
                                const float* __restrict__ Wv) {
    const int z = blockIdx.z;
    const float* B = (z == 0) ? Wq : (z == 1) ? Wk : Wv;
    gemm_tile_tf32(x, B, &g_qkv[z][0]);
}

__global__ void gemm_out_kernel(const float* __restrict__ Wp,
                                float* __restrict__ out) {
    gemm_tile_tf32(g_att, Wp, out);
}

// ---------------------------------------------------------------------------
// Epilogue: v = (1-l)*v + l*vi ; q,k = rope(rmsnorm(q|k)); relayout to [h][t][64]
// One warp per (t, head).
// ---------------------------------------------------------------------------
__global__ void qkv_epilogue_kernel(const float* __restrict__ vi,
                                    const float* __restrict__ lamb) {
    const int w = (blockIdx.x * blockDim.x + threadIdx.x) >> 5;
    const int lane = threadIdx.x & 31;
    if (w >= T * NH) return;
    const int t = w / NH;
    const int h = w % NH;

    const int src = t * DIM + h * HD;
    const int dst = (h * T + t) * HD;

    const float invf = (float)pow(10000.0, -(double)lane / 32.0);
    const float ang = (float)t * invf;
    float sa, ca;
    sincosf(ang, &sa, &ca);

    const float eps = 1.1920929e-07f;

    {
        float a = g_qkv[0][src + lane];
        float b = g_qkv[0][src + 32 + lane];
        float ss = a * a + b * b;
#pragma unroll
        for (int m = 16; m >= 1; m >>= 1) ss += __shfl_xor_sync(0xffffffffu, ss, m);
        float r = rsqrtf(ss * (1.0f / 64.0f) + eps);
        a *= r; b *= r;
        g_q[dst + lane]      = a * ca + b * sa;
        g_q[dst + 32 + lane] = -a * sa + b * ca;
    }
    {
        float a = g_qkv[1][src + lane];
        float b = g_qkv[1][src + 32 + lane];
        float ss = a * a + b * b;
#pragma unroll
        for (int m = 16; m >= 1; m >>= 1) ss += __shfl_xor_sync(0xffffffffu, ss, m);
        float r = rsqrtf(ss * (1.0f / 64.0f) + eps);
        a *= r; b *= r;
        g_k[dst + lane]      = a * ca + b * sa;
        g_k[dst + 32 + lane] = -a * sa + b * ca;
    }
    {
        const float l = lamb[0];
        float va = g_qkv[2][src + lane];
        float vb = g_qkv[2][src + 32 + lane];
        float ia = vi[src + lane];
        float ib = vi[src + 32 + lane];
        g_v[dst + lane]      = (1.0f - l) * va + l * ia;
        g_v[dst + 32 + lane] = (1.0f - l) * vb + l * ib;
    }
}

// ---------------------------------------------------------------------------
// Flash attention, causal, TF32 tensor cores, FIXED-MAX softmax.
// After rms_norm, |q|=|k|=8, so scores = q.k/8 in [-8,8]: exp cannot overflow,
// so no online max/rescale; P = exp(s), l = sum P, normalize at the end.
// Q tile = 128 rows per block (2x the R2 version: same sync count per
// iteration, double the FLOPs). 256 threads = 8 warps in a 4x2 grid, each
// warp owns a 32x32 sub-tile (2x2 m16n16k8 fragments). O stays in registers.
// 96KB dynamic smem; __launch_bounds__(256,2) -> 2 CTAs/SM overlap syncs.
// Reversed qt order: biggest blocks launch first (less makespan tail).
// ---------------------------------------------------------------------------
#define QT 128

__global__ __launch_bounds__(256, 2) void attn_kernel() {
    extern __shared__ float sm[];
    float* Qs = sm;               // 128x64 (tf32)
    float* Ks = Qs + QT * HD;     // 64x64 (tf32)
    float* Vs = Ks + 64 * HD;     // 64x64 (tf32)
    float* Ss = Vs + 64 * HD;     // 128x64 scores -> P (tf32), then O
    __shared__ float lrow[QT];

    const int qt = (int)gridDim.x - 1 - (int)blockIdx.x;  // big tiles first
    const int h = blockIdx.y;
    const int tid = threadIdx.x;
    const int wid = tid >> 5;
    const int warp_m = wid >> 1;  // 0..3 -> rows 32*warp_m
    const int warp_n = wid & 1;   // 0..1 -> cols 32*warp_n
    const int q0 = qt * QT;

    const float* qh = g_q + h * T * HD;
    const float* kh = g_k + h * T * HD;
    const float* vh = g_v + h * T * HD;

    // load Q tile (tf32): 128x64
    for (int v = tid; v < QT * 16; v += 256) {
        int r = v >> 4, c4 = (v & 15) * 4;
        float4 q = *(const float4*)&qh[(q0 + r) * HD + c4];
        Qs[r * HD + c4 + 0] = tf32c(q.x);
        Qs[r * HD + c4 + 1] = tf32c(q.y);
        Qs[r * HD + c4 + 2] = tf32c(q.z);
        Qs[r * HD + c4 + 3] = tf32c(q.w);
    }
    if (tid < QT) lrow[tid] = 0.0f;

    // persistent O fragments: 32x32 per warp
    wmma::fragment<wmma::accumulator, 16, 16, 8, float> oacc[2][2];
#pragma unroll
    for (int i = 0; i < 2; i++)
#pragma unroll
        for (int j = 0; j < 2; j++) wmma::fill_fragment(oacc[i][j], 0.0f);

    const int row = tid >> 1;   // 0..127 softmax row
    const int cg = tid & 1;     // col half (32 cols each)

    const int kt_max = (q0 + QT - 1) / 64;  // inclusive
    for (int kt = 0; kt <= kt_max; kt++) {
        __syncthreads();  // previous iteration's readers of Ks/Vs/Ss done
        for (int v = tid; v < 64 * 16; v += 256) {
            int r = v >> 4, c4 = (v & 15) * 4;
            float4 k = *(const float4*)&kh[(kt * 64 + r) * HD + c4];
            float4 vv = *(const float4*)&vh[(kt * 64 + r) * HD + c4];
            Ks[r * HD + c4 + 0] = tf32c(k.x);
            Ks[r * HD + c4 + 1] = tf32c(k.y);
            Ks[r * HD + c4 + 2] = tf32c(k.z);
            Ks[r * HD + c4 + 3] = tf32c(k.w);
            Vs[r * HD + c4 + 0] = tf32c(vv.x);
            Vs[r * HD + c4 + 1] = tf32c(vv.y);
            Vs[r * HD + c4 + 2] = tf32c(vv.z);
            Vs[r * HD + c4 + 3] = tf32c(vv.w);
        }
        __syncthreads();

        // S = Q . K^T  (warp: 32 rows x 32 cols)
        {
            wmma::fragment<wmma::accumulator, 16, 16, 8, float> sacc[2][2];
#pragma unroll
            for (int i = 0; i < 2; i++)
#pragma unroll
                for (int j = 0; j < 2; j++) wmma::fill_fragment(sacc[i][j], 0.0f);
#pragma unroll
            for (int kk = 0; kk < HD; kk += 8) {
                wmma::fragment<wmma::matrix_a, 16, 16, 8, wmma::precision::tf32, wmma::row_major> af[2];
                wmma::fragment<wmma::matrix_b, 16, 16, 8, wmma::precision::tf32, wmma::col_major> bf[2];
#pragma unroll
                for (int i = 0; i < 2; i++)
                    wmma::load_matrix_sync(af[i], &Qs[(warp_m * 32 + i * 16) * HD + kk], HD);
#pragma unroll
                for (int j = 0; j < 2; j++)
                    wmma::load_matrix_sync(bf[j], &Ks[(warp_n * 32 + j * 16) * HD + kk], HD);
#pragma unroll
                for (int i = 0; i < 2; i++)
#pragma unroll
                    for (int j = 0; j < 2; j++)
                        wmma::mma_sync(sacc[i][j], af[i], bf[j], sacc[i][j]);
            }
#pragma unroll
            for (int i = 0; i < 2; i++)
#pragma unroll
                for (int j = 0; j < 2; j++)
                    wmma::store_matrix_sync(
                        &Ss[(warp_m * 32 + i * 16) * HD + warp_n * 32 + j * 16],
                        sacc[i][j], HD, wmma::mem_row_major);
        }
        __syncthreads();

        // P = exp(S*scale) with causal mask; accumulate row sums
        {
            const int grow = q0 + row;
            const int gcol0 = kt * 64 + cg * 32;
            float rs = 0.0f;
#pragma unroll
            for (int c = 0; c < 32; c++) {
                int cc = cg * 32 + c;
                float p = (gcol0 + c > grow)
                              ? 0.0f
                              : __expf(Ss[row * HD + cc] * 0.125f);
                rs += p;
                Ss[row * HD + cc] = tf32c(p);
            }
            rs += __shfl_xor_sync(0xffffffffu, rs, 1);
            if (cg == 0) lrow[row] += rs;
        }
        __syncthreads();

        // O += P . V (accumulate in registers)
#pragma unroll
        for (int kk = 0; kk < 64; kk += 8) {
            wmma::fragment<wmma::matrix_a, 16, 16, 8, wmma::precision::tf32, wmma::row_major> af[2];
            wmma::fragment<wmma::matrix_b, 16, 16, 8, wmma::precision::tf32, wmma::row_major> bf[2];
#pragma unroll
            for (int i = 0; i < 2; i++)
                wmma::load_matrix_sync(af[i], &Ss[(warp_m * 32 + i * 16) * HD + kk], HD);
#pragma unroll
            for (int j = 0; j < 2; j++)
                wmma::load_matrix_sync(bf[j], &Vs[kk * HD + warp_n * 32 + j * 16], HD);
#pragma unroll
            for (int i = 0; i < 2; i++)
#pragma unroll
                for (int j = 0; j < 2; j++)
                    wmma::mma_sync(oacc[i][j], af[i], bf[j], oacc[i][j]);
        }
    }

    // dump O fragments once, normalize, write out in [t][768] layout
    __syncthreads();
#pragma unroll
    for (int i = 0; i < 2; i++)
#pragma unroll
        for (int j = 0; j < 2; j++)
            wmma::store_matrix_sync(
                &Ss[(warp_m * 32 + i * 16) * HD + warp_n * 32 + j * 16],
                oacc[i][j], HD, wmma::mem_row_major);
    __syncthreads();
    {
        float inv = 1.0f / lrow[row];
#pragma unroll
        for (int c = 0; c < 32; c++)
            g_att[(q0 + row) * DIM + h * HD + cg * 32 + c] = Ss[row * HD + cg * 32 + c] * inv;
    }
}

// ---------------------------------------------------------------------------
extern "C" void kernel_launch(void* const* d_in, const int* in_sizes, int n_in,
                              void* d_out, int out_size) {
    const float* x    = (const float*)d_in[0];
    const float* vi   = (const float*)d_in[1];
    const float* Wq   = (const float*)d_in[2];
    const float* Wk   = (const float*)d_in[3];
    const float* Wv   = (const float*)d_in[4];
    const float* Wp   = (const float*)d_in[5];
    const float* lamb = (const float*)d_in[6];
    float* out = (float*)d_out;

    const int attn_smem = (QT * HD + 64 * HD + 64 * HD + QT * HD) * sizeof(float);  // 96KB

    static bool attr_set = false;
    if (!attr_set) {
        cudaFuncSetAttribute(attn_kernel,
                             cudaFuncAttributeMaxDynamicSharedMemorySize,
                             attn_smem);
        attr_set = true;
    }

    dim3 gqkv(DIM / BN, T / BM, 3);
    gemm_qkv_kernel<<<gqkv, 256>>>(x, Wq, Wk, Wv);

    qkv_epilogue_kernel<<<(T * NH * 32) / 256, 256>>>(vi, lamb);

    dim3 gattn(T / QT, NH, 1);
    attn_kernel<<<gattn, 256, attn_smem>>>();

    dim3 gout(DIM / BN, T / BM, 1);
    gemm_out_kernel<<<gout, 256>>>(Wp, out);
}

// round 10
// speedup vs baseline: 2.2351x; 1.8263x over previous
#include <cuda_runtime.h>
#include <mma.h>
#include <math.h>

using namespace nvcuda;

#define T 2048
#define DIM 768
#define NH 12
#define HD 64

// Scratch (allocation-free: __device__ globals)
__device__ float g_qkv[3][T * DIM];   // raw q,k,v projections, [t][768] layout
__device__ float g_q[T * DIM];        // [h][t][64]
__device__ float g_k[T * DIM];        // [h][t][64]
__device__ float g_v[T * DIM];        // [h][t][64]
__device__ float g_att[T * DIM];      // attention output, [t][768] layout

__device__ __forceinline__ float tf32c(float x) { return wmma::__float_to_tf32(x); }

// ---------------------------------------------------------------------------
// TF32 wmma GEMM-NT (measured-good): C[m][n] = sum_k A[m*DIM+k]*B[n*DIM+k]
// Block tile 128x64, 8 warps (4x2), warp tile 32x32 (2x2 m16n16k8), BK=16.
// ---------------------------------------------------------------------------
#define BM 128
#define BN 64
#define BK 16

__device__ __forceinline__ void gemm_tile_tf32(const float* __restrict__ A,
                                               const float* __restrict__ B,
                                               float* __restrict__ C) {
    __shared__ float As[BM][BK];   // [m][k]
    __shared__ float Bs[BN][BK];   // [n][k]
    const int tid = threadIdx.x;
    const int wid = tid >> 5;
    const int m0 = blockIdx.y * BM, n0 = blockIdx.x * BN;
    const int warp_m = wid >> 1;   // 0..3
    const int warp_n = wid & 1;    // 0..1

    wmma::fragment<wmma::accumulator, 16, 16, 8, float> acc[2][2];
#pragma unroll
    for (int i = 0; i < 2; i++)
#pragma unroll
        for (int j = 0; j < 2; j++) wmma::fill_fragment(acc[i][j], 0.0f);

    for (int k0 = 0; k0 < DIM; k0 += BK) {
        __syncthreads();
#pragma unroll
        for (int v = tid; v < BM * BK / 4; v += 256) {
            int r = v >> 2, c4 = (v & 3) * 4;
            float4 a = *(const float4*)&A[(m0 + r) * DIM + k0 + c4];
            As[r][c4 + 0] = tf32c(a.x);
            As[r][c4 + 1] = tf32c(a.y);
            As[r][c4 + 2] = tf32c(a.z);
            As[r][c4 + 3] = tf32c(a.w);
        }
        {
            int v = tid;  // BN*BK/4 == 256
            int r = v >> 2, c4 = (v & 3) * 4;
            float4 b = *(const float4*)&B[(n0 + r) * DIM + k0 + c4];
            Bs[r][c4 + 0] = tf32c(b.x);
            Bs[r][c4 + 1] = tf32c(b.y);
            Bs[r][c4 + 2] = tf32c(b.z);
            Bs[r][c4 + 3] = tf32c(b.w);
        }
        __syncthreads();
#pragma unroll
        for (int kk = 0; kk < BK; kk += 8) {
            wmma::fragment<wmma::matrix_a, 16, 16, 8, wmma::precision::tf32, wmma::row_major> af[2];
            wmma::fragment<wmma::matrix_b, 16, 16, 8, wmma::precision::tf32, wmma::col_major> bf[2];
#pragma unroll
            for (int i = 0; i < 2; i++)
                wmma::load_matrix_sync(af[i], &As[warp_m * 32 + i * 16][kk], BK);
#pragma unroll
            for (int j = 0; j < 2; j++)
                wmma::load_matrix_sync(bf[j], &Bs[warp_n * 32 + j * 16][kk], BK);
#pragma unroll
            for (int i = 0; i < 2; i++)
#pragma unroll
                for (int j = 0; j < 2; j++)
                    wmma::mma_sync(acc[i][j], af[i], bf[j], acc[i][j]);
        }
    }
#pragma unroll
    for (int i = 0; i < 2; i++)
#pragma unroll
        for (int j = 0; j < 2; j++)
            wmma::store_matrix_sync(
                &C[(m0 + warp_m * 32 + i * 16) * DIM + n0 + warp_n * 32 + j * 16],
                acc[i][j], DIM, wmma::mem_row_major);
}

__global__ void gemm_qkv_kernel(const float* __restrict__ x,
                                const float* __restrict__ Wq,
                                const float* __restrict__ Wk,
                                const float* __restrict__ Wv) {
    const int z = blockIdx.z;
    const float* B = (z == 0) ? Wq : (z == 1) ? Wk : Wv;
    gemm_tile_tf32(x, B, &g_qkv[z][0]);
}

__global__ void gemm_out_kernel(const float* __restrict__ Wp,
                                float* __restrict__ out) {
    gemm_tile_tf32(g_att, Wp, out);
}

// ---------------------------------------------------------------------------
// Epilogue: v = (1-l)*v + l*vi ; q,k = rope(rmsnorm(q|k)); relayout to [h][t][64]
// One warp per (t, head). RoPE inv_freq via fp32 exp2f (MUFU), NOT double pow:
// pow(double) ran on the ~18 cyc/op FP64 pipe and dominated this kernel.
// ---------------------------------------------------------------------------
__global__ void qkv_epilogue_kernel(const float* __restrict__ vi,
                                    const float* __restrict__ lamb) {
    const int w = (blockIdx.x * blockDim.x + threadIdx.x) >> 5;
    const int lane = threadIdx.x & 31;
    if (w >= T * NH) return;
    const int t = w / NH;
    const int h = w % NH;

    const int src = t * DIM + h * HD;
    const int dst = (h * T + t) * HD;

    // inv_freq = 10000^(-lane/32) = 2^(-log2(10000) * lane/32)
    const float invf = exp2f(-13.287712379549449f * (float)lane * (1.0f / 32.0f));
    const float ang = (float)t * invf;
    float sa, ca;
    sincosf(ang, &sa, &ca);

    const float eps = 1.1920929e-07f;

    {
        float a = g_qkv[0][src + lane];
        float b = g_qkv[0][src + 32 + lane];
        float ss = a * a + b * b;
#pragma unroll
        for (int m = 16; m >= 1; m >>= 1) ss += __shfl_xor_sync(0xffffffffu, ss, m);
        float r = rsqrtf(ss * (1.0f / 64.0f) + eps);
        a *= r; b *= r;
        g_q[dst + lane]      = a * ca + b * sa;
        g_q[dst + 32 + lane] = -a * sa + b * ca;
    }
    {
        float a = g_qkv[1][src + lane];
        float b = g_qkv[1][src + 32 + lane];
        float ss = a * a + b * b;
#pragma unroll
        for (int m = 16; m >= 1; m >>= 1) ss += __shfl_xor_sync(0xffffffffu, ss, m);
        float r = rsqrtf(ss * (1.0f / 64.0f) + eps);
        a *= r; b *= r;
        g_k[dst + lane]      = a * ca + b * sa;
        g_k[dst + 32 + lane] = -a * sa + b * ca;
    }
    {
        const float l = lamb[0];
        float va = g_qkv[2][src + lane];
        float vb = g_qkv[2][src + 32 + lane];
        float ia = vi[src + lane];
        float ib = vi[src + 32 + lane];
        g_v[dst + lane]      = (1.0f - l) * va + l * ia;
        g_v[dst + 32 + lane] = (1.0f - l) * vb + l * ib;
    }
}

// ---------------------------------------------------------------------------
// Flash attention, causal, TF32 tensor cores, FIXED-MAX softmax (R2 config:
// QT=64, measured-good). After rms_norm, |q|=|k|=8 so scores in [-8,8]:
// no online max needed. O accumulates in register fragments; normalize once.
// Block per (q-tile of 64, head), 256 threads = 8 warps (4m x 2n).
// Big tiles launch first (reversed qt) to shrink the makespan tail.
// ---------------------------------------------------------------------------
__global__ void attn_kernel() {
    extern __shared__ float sm[];
    float* Qs = sm;              // 64x64 (tf32)
    float* Ks = Qs + 4096;       // 64x64 (tf32)
    float* Vs = Ks + 4096;       // 64x64 (tf32)
    float* Ss = Vs + 4096;       // 64x64 scores -> P (tf32), then O at the end
    __shared__ float lrow[64];

    const int qt = (int)gridDim.x - 1 - (int)blockIdx.x;  // big tiles first
    const int h = blockIdx.y;
    const int tid = threadIdx.x;
    const int wid = tid >> 5;
    const int warp_m = wid >> 1;  // 0..3
    const int warp_n = wid & 1;   // 0..1
    const int q0 = qt * 64;

    const float* qh = g_q + h * T * HD;
    const float* kh = g_k + h * T * HD;
    const float* vh = g_v + h * T * HD;

    // load Q tile (tf32)
    for (int v = tid; v < 64 * 16; v += 256) {
        int r = v >> 4, c4 = (v & 15) * 4;
        float4 q = *(const float4*)&qh[(q0 + r) * HD + c4];
        Qs[r * 64 + c4 + 0] = tf32c(q.x);
        Qs[r * 64 + c4 + 1] = tf32c(q.y);
        Qs[r * 64 + c4 + 2] = tf32c(q.z);
        Qs[r * 64 + c4 + 3] = tf32c(q.w);
    }
    if (tid < 64) lrow[tid] = 0.0f;

    // O accumulator fragments: 16 rows x 32 cols per warp, live whole loop
    wmma::fragment<wmma::accumulator, 16, 16, 8, float> oacc[2];
#pragma unroll
    for (int j = 0; j < 2; j++) wmma::fill_fragment(oacc[j], 0.0f);

    const int row = tid >> 2;     // 0..63 softmax row
    const int cg = tid & 3;       // col group, 16 cols each

    for (int kt = 0; kt <= qt; kt++) {
        __syncthreads();  // previous iter's PV readers of Ks/Vs/Ss done
        for (int v = tid; v < 64 * 16; v += 256) {
            int r = v >> 4, c4 = (v & 15) * 4;
            float4 k = *(const float4*)&kh[(kt * 64 + r) * HD + c4];
            float4 vv = *(const float4*)&vh[(kt * 64 + r) * HD + c4];
            Ks[r * 64 + c4 + 0] = tf32c(k.x);
            Ks[r * 64 + c4 + 1] = tf32c(k.y);
            Ks[r * 64 + c4 + 2] = tf32c(k.z);
            Ks[r * 64 + c4 + 3] = tf32c(k.w);
            Vs[r * 64 + c4 + 0] = tf32c(vv.x);
            Vs[r * 64 + c4 + 1] = tf32c(vv.y);
            Vs[r * 64 + c4 + 2] = tf32c(vv.z);
            Vs[r * 64 + c4 + 3] = tf32c(vv.w);
        }
        __syncthreads();

        // S = Q . K^T
        {
            wmma::fragment<wmma::accumulator, 16, 16, 8, float> sacc[2];
#pragma unroll
            for (int j = 0; j < 2; j++) wmma::fill_fragment(sacc[j], 0.0f);
#pragma unroll
            for (int kk = 0; kk < 64; kk += 8) {
                wmma::fragment<wmma::matrix_a, 16, 16, 8, wmma::precision::tf32, wmma::row_major> af;
                wmma::fragment<wmma::matrix_b, 16, 16, 8, wmma::precision::tf32, wmma::col_major> bf[2];
                wmma::load_matrix_sync(af, &Qs[(warp_m * 16) * 64 + kk], 64);
#pragma unroll
                for (int j = 0; j < 2; j++)
                    wmma::load_matrix_sync(bf[j], &Ks[(warp_n * 32 + j * 16) * 64 + kk], 64);
#pragma unroll
                for (int j = 0; j < 2; j++)
                    wmma::mma_sync(sacc[j], af, bf[j], sacc[j]);
            }
#pragma unroll
            for (int j = 0; j < 2; j++)
                wmma::store_matrix_sync(&Ss[(warp_m * 16) * 64 + warp_n * 32 + j * 16],
                                        sacc[j], 64, wmma::mem_row_major);
        }
        __syncthreads();

        // P = exp(S*scale) with causal mask; accumulate row sums (no max needed)
        {
            const bool diag = (kt == qt);
            float rs = 0.0f;
#pragma unroll
            for (int c = 0; c < 16; c++) {
                int cc = cg * 16 + c;
                float p;
                if (diag && cc > row) {
                    p = 0.0f;
                } else {
                    p = __expf(Ss[row * 64 + cc] * 0.125f);
                }
                rs += p;
                Ss[row * 64 + cc] = tf32c(p);
            }
            rs += __shfl_xor_sync(0xffffffffu, rs, 1);
            rs += __shfl_xor_sync(0xffffffffu, rs, 2);
            if (cg == 0) lrow[row] += rs;
        }
        __syncthreads();

        // O += P . V (accumulate in registers)
#pragma unroll
        for (int kk = 0; kk < 64; kk += 8) {
            wmma::fragment<wmma::matrix_a, 16, 16, 8, wmma::precision::tf32, wmma::row_major> af;
            wmma::fragment<wmma::matrix_b, 16, 16, 8, wmma::precision::tf32, wmma::row_major> bf[2];
            wmma::load_matrix_sync(af, &Ss[(warp_m * 16) * 64 + kk], 64);
#pragma unroll
            for (int j = 0; j < 2; j++)
                wmma::load_matrix_sync(bf[j], &Vs[kk * 64 + warp_n * 32 + j * 16], 64);
#pragma unroll
            for (int j = 0; j < 2; j++)
                wmma::mma_sync(oacc[j], af, bf[j], oacc[j]);
        }
    }

    // dump O fragments once, normalize, write out in [t][768] layout
    __syncthreads();
#pragma unroll
    for (int j = 0; j < 2; j++)
        wmma::store_matrix_sync(&Ss[(warp_m * 16) * 64 + warp_n * 32 + j * 16],
                                oacc[j], 64, wmma::mem_row_major);
    __syncthreads();
    {
        float inv = 1.0f / lrow[row];
#pragma unroll
        for (int c = 0; c < 16; c++)
            g_att[(q0 + row) * DIM + h * HD + cg * 16 + c] = Ss[row * 64 + cg * 16 + c] * inv;
    }
}

// ---------------------------------------------------------------------------
extern "C" void kernel_launch(void* const* d_in, const int* in_sizes, int n_in,
                              void* d_out, int out_size) {
    const float* x    = (const float*)d_in[0];
    const float* vi   = (const float*)d_in[1];
    const float* Wq   = (const float*)d_in[2];
    const float* Wk   = (const float*)d_in[3];
    const float* Wv   = (const float*)d_in[4];
    const float* Wp   = (const float*)d_in[5];
    const float* lamb = (const float*)d_in[6];
    float* out = (float*)d_out;

    static bool attr_set = false;
    if (!attr_set) {
        cudaFuncSetAttribute(attn_kernel,
                             cudaFuncAttributeMaxDynamicSharedMemorySize,
                             4 * 4096 * sizeof(float));
        attr_set = true;
    }

    dim3 gqkv(DIM / BN, T / BM, 3);
    gemm_qkv_kernel<<<gqkv, 256>>>(x, Wq, Wk, Wv);

    qkv_epilogue_kernel<<<(T * NH * 32) / 256, 256>>>(vi, lamb);

    dim3 gattn(T / 64, NH, 1);
    attn_kernel<<<gattn, 256, 4 * 4096 * sizeof(float)>>>();

    dim3 gout(DIM / BN, T / BM, 1);
    gemm_out_kernel<<<gout, 256>>>(Wp, out);
}

// round 11
// speedup vs baseline: 2.5771x; 1.1530x over previous
#include <cuda_runtime.h>
#include <mma.h>
#include <math.h>

using namespace nvcuda;

#define T 2048
#define DIM 768
#define NH 12
#define HD 64
#define NCHUNK 4          // kt chunks per q-tile (8 kt-tiles = 512 keys each)
#define CHUNK_KT 8

// Scratch (allocation-free: __device__ globals)
__device__ float g_qkv[3][T * DIM];        // raw q,k,v projections, [t][768]
__device__ float g_q[T * DIM];             // [h][t][64]
__device__ float g_k[T * DIM];             // [h][t][64]
__device__ float g_v[T * DIM];             // [h][t][64]
__device__ float g_att[T * DIM];           // attention output, [t][768]
__device__ float g_opart[NCHUNK][T * DIM]; // unnormalized partial O per chunk
__device__ float g_lpart[NCHUNK][NH * T];  // partial row sums per chunk

__device__ __forceinline__ float tf32c(float x) { return wmma::__float_to_tf32(x); }

// ---------------------------------------------------------------------------
// TF32 wmma GEMM-NT, double-buffered BK=16 (same smem layout as the
// measured-good version; one __syncthreads per k-step instead of two).
// Block tile 128x64, 8 warps (4x2), warp tile 32x32 (2x2 m16n16k8).
// ---------------------------------------------------------------------------
#define BM 128
#define BN 64
#define BK 16

__device__ __forceinline__ void gemm_tile_tf32(const float* __restrict__ A,
                                               const float* __restrict__ B,
                                               float* __restrict__ C) {
    __shared__ float As[2][BM][BK];
    __shared__ float Bs[2][BN][BK];
    const int tid = threadIdx.x;
    const int wid = tid >> 5;
    const int m0 = blockIdx.y * BM, n0 = blockIdx.x * BN;
    const int warp_m = wid >> 1;   // 0..3
    const int warp_n = wid & 1;    // 0..1
    const int r = tid >> 2;        // 0..63
    const int c4 = (tid & 3) * 4;  // 0..12

    wmma::fragment<wmma::accumulator, 16, 16, 8, float> acc[2][2];
#pragma unroll
    for (int i = 0; i < 2; i++)
#pragma unroll
        for (int j = 0; j < 2; j++) wmma::fill_fragment(acc[i][j], 0.0f);

    float4 pa0, pa1, pb;
    auto load_regs = [&](int k0) {
        pa0 = *(const float4*)&A[(m0 + r) * DIM + k0 + c4];
        pa1 = *(const float4*)&A[(m0 + 64 + r) * DIM + k0 + c4];
        pb  = *(const float4*)&B[(n0 + r) * DIM + k0 + c4];
    };
    auto store_smem = [&](int buf) {
        As[buf][r][c4 + 0] = tf32c(pa0.x); As[buf][r][c4 + 1] = tf32c(pa0.y);
        As[buf][r][c4 + 2] = tf32c(pa0.z); As[buf][r][c4 + 3] = tf32c(pa0.w);
        As[buf][64 + r][c4 + 0] = tf32c(pa1.x); As[buf][64 + r][c4 + 1] = tf32c(pa1.y);
        As[buf][64 + r][c4 + 2] = tf32c(pa1.z); As[buf][64 + r][c4 + 3] = tf32c(pa1.w);
        Bs[buf][r][c4 + 0] = tf32c(pb.x); Bs[buf][r][c4 + 1] = tf32c(pb.y);
        Bs[buf][r][c4 + 2] = tf32c(pb.z); Bs[buf][r][c4 + 3] = tf32c(pb.w);
    };

    const int NSTEP = DIM / BK;  // 48
    load_regs(0);
    store_smem(0);

    for (int s = 0; s < NSTEP; s++) {
        __syncthreads();  // buf (s&1) ready; everyone done with step s-1
        const int buf = s & 1;
        if (s + 1 < NSTEP) load_regs((s + 1) * BK);
#pragma unroll
        for (int kk = 0; kk < BK; kk += 8) {
            wmma::fragment<wmma::matrix_a, 16, 16, 8, wmma::precision::tf32, wmma::row_major> af[2];
            wmma::fragment<wmma::matrix_b, 16, 16, 8, wmma::precision::tf32, wmma::col_major> bf[2];
#pragma unroll
            for (int i = 0; i < 2; i++)
                wmma::load_matrix_sync(af[i], &As[buf][warp_m * 32 + i * 16][kk], BK);
#pragma unroll
            for (int j = 0; j < 2; j++)
                wmma::load_matrix_sync(bf[j], &Bs[buf][warp_n * 32 + j * 16][kk], BK);
#pragma unroll
            for (int i = 0; i < 2; i++)
#pragma unroll
                for (int j = 0; j < 2; j++)
                    wmma::mma_sync(acc[i][j], af[i], bf[j], acc[i][j]);
        }
        if (s + 1 < NSTEP) store_smem((s + 1) & 1);
    }
#pragma unroll
    for (int i = 0; i < 2; i++)
#pragma unroll
        for (int j = 0; j < 2; j++)
            wmma::store_matrix_sync(
                &C[(m0 + warp_m * 32 + i * 16) * DIM + n0 + warp_n * 32 + j * 16],
                acc[i][j], DIM, wmma::mem_row_major);
}

__global__ void gemm_qkv_kernel(const float* __restrict__ x,
                                const float* __restrict__ Wq,
                                const float* __restrict__ Wk,
                                const float* __restrict__ Wv) {
    const int z = blockIdx.z;
    const float* B = (z == 0) ? Wq : (z == 1) ? Wk : Wv;
    gemm_tile_tf32(x, B, &g_qkv[z][0]);
}

__global__ void gemm_out_kernel(const float* __restrict__ Wp,
                                float* __restrict__ out) {
    gemm_tile_tf32(g_att, Wp, out);
}

// ---------------------------------------------------------------------------
// Epilogue: v = (1-l)*v + l*vi ; q,k = rope(rmsnorm(q|k)); relayout to [h][t][64]
// One warp per (t, head). fp32 exp2f for inv_freq (no FP64 pipe).
// ---------------------------------------------------------------------------
__global__ void qkv_epilogue_kernel(const float* __restrict__ vi,
                                    const float* __restrict__ lamb) {
    const int w = (blockIdx.x * blockDim.x + threadIdx.x) >> 5;
    const int lane = threadIdx.x & 31;
    if (w >= T * NH) return;
    const int t = w / NH;
    const int h = w % NH;

    const int src = t * DIM + h * HD;
    const int dst = (h * T + t) * HD;

    const float invf = exp2f(-13.287712379549449f * (float)lane * (1.0f / 32.0f));
    const float ang = (float)t * invf;
    float sa, ca;
    sincosf(ang, &sa, &ca);

    const float eps = 1.1920929e-07f;

    {
        float a = g_qkv[0][src + lane];
        float b = g_qkv[0][src + 32 + lane];
        float ss = a * a + b * b;
#pragma unroll
        for (int m = 16; m >= 1; m >>= 1) ss += __shfl_xor_sync(0xffffffffu, ss, m);
        float r = rsqrtf(ss * (1.0f / 64.0f) + eps);
        a *= r; b *= r;
        g_q[dst + lane]      = a * ca + b * sa;
        g_q[dst + 32 + lane] = -a * sa + b * ca;
    }
    {
        float a = g_qkv[1][src + lane];
        float b = g_qkv[1][src + 32 + lane];
        float ss = a * a + b * b;
#pragma unroll
        for (int m = 16; m >= 1; m >>= 1) ss += __shfl_xor_sync(0xffffffffu, ss, m);
        float r = rsqrtf(ss * (1.0f / 64.0f) + eps);
        a *= r; b *= r;
        g_k[dst + lane]      = a * ca + b * sa;
        g_k[dst + 32 + lane] = -a * sa + b * ca;
    }
    {
        const float l = lamb[0];
        float va = g_qkv[2][src + lane];
        float vb = g_qkv[2][src + 32 + lane];
        float ia = vi[src + lane];
        float ib = vi[src + 32 + lane];
        g_v[dst + lane]      = (1.0f - l) * va + l * ia;
        g_v[dst + 32 + lane] = (1.0f - l) * vb + l * ib;
    }
}

// ---------------------------------------------------------------------------
// Split-K flash attention, causal, TF32, FIXED-MAX softmax.
// Fixed-max (valid because rms_norm gives |q|=|k|=8 -> scores in [-8,8])
// makes attention a pure sum over kt, so the kt range is split into chunks
// of 8 tiles across blockIdx.z. Each chunk CTA writes unnormalized partial
// O and partial row-sum l to its own buffer (no atomics, deterministic);
// attn_reduce sums <=4 partials and normalizes. Critical path drops from
// 32 serial kt-iterations to 8 (plus reduce), and work is near-uniform.
// ---------------------------------------------------------------------------
__global__ void attn_kernel() {
    const int qt = blockIdx.x;
    const int h = blockIdx.y;
    const int c = blockIdx.z;
    if (CHUNK_KT * c > qt) return;  // chunk beyond causal range

    extern __shared__ float sm[];
    float* Qs = sm;              // 64x64 (tf32)
    float* Ks = Qs + 4096;       // 64x64 (tf32)
    float* Vs = Ks + 4096;       // 64x64 (tf32)
    float* Ss = Vs + 4096;       // 64x64 scores -> P (tf32), then O at the end
    __shared__ float lrow[64];

    const int tid = threadIdx.x;
    const int wid = tid >> 5;
    const int warp_m = wid >> 1;  // 0..3
    const int warp_n = wid & 1;   // 0..1
    const int q0 = qt * 64;

    const float* qh = g_q + h * T * HD;
    const float* kh = g_k + h * T * HD;
    const float* vh = g_v + h * T * HD;

    // load Q tile (tf32)
    for (int v = tid; v < 64 * 16; v += 256) {
        int r = v >> 4, c4 = (v & 15) * 4;
        float4 q = *(const float4*)&qh[(q0 + r) * HD + c4];
        Qs[r * 64 + c4 + 0] = tf32c(q.x);
        Qs[r * 64 + c4 + 1] = tf32c(q.y);
        Qs[r * 64 + c4 + 2] = tf32c(q.z);
        Qs[r * 64 + c4 + 3] = tf32c(q.w);
    }
    if (tid < 64) lrow[tid] = 0.0f;

    wmma::fragment<wmma::accumulator, 16, 16, 8, float> oacc[2];
#pragma unroll
    for (int j = 0; j < 2; j++) wmma::fill_fragment(oacc[j], 0.0f);

    const int row = tid >> 2;     // 0..63 softmax row
    const int cg = tid & 3;       // col group, 16 cols each

    const int kt0 = CHUNK_KT * c;
    const int kt1 = min(CHUNK_KT * c + CHUNK_KT - 1, qt);

    for (int kt = kt0; kt <= kt1; kt++) {
        __syncthreads();  // previous iter's PV readers of Ks/Vs/Ss done
        for (int v = tid; v < 64 * 16; v += 256) {
            int r = v >> 4, c4 = (v & 15) * 4;
            float4 k = *(const float4*)&kh[(kt * 64 + r) * HD + c4];
            float4 vv = *(const float4*)&vh[(kt * 64 + r) * HD + c4];
            Ks[r * 64 + c4 + 0] = tf32c(k.x);
            Ks[r * 64 + c4 + 1] = tf32c(k.y);
            Ks[r * 64 + c4 + 2] = tf32c(k.z);
            Ks[r * 64 + c4 + 3] = tf32c(k.w);
            Vs[r * 64 + c4 + 0] = tf32c(vv.x);
            Vs[r * 64 + c4 + 1] = tf32c(vv.y);
            Vs[r * 64 + c4 + 2] = tf32c(vv.z);
            Vs[r * 64 + c4 + 3] = tf32c(vv.w);
        }
        __syncthreads();

        // S = Q . K^T
        {
            wmma::fragment<wmma::accumulator, 16, 16, 8, float> sacc[2];
#pragma unroll
            for (int j = 0; j < 2; j++) wmma::fill_fragment(sacc[j], 0.0f);
#pragma unroll
            for (int kk = 0; kk < 64; kk += 8) {
                wmma::fragment<wmma::matrix_a, 16, 16, 8, wmma::precision::tf32, wmma::row_major> af;
                wmma::fragment<wmma::matrix_b, 16, 16, 8, wmma::precision::tf32, wmma::col_major> bf[2];
                wmma::load_matrix_sync(af, &Qs[(warp_m * 16) * 64 + kk], 64);
#pragma unroll
                for (int j = 0; j < 2; j++)
                    wmma::load_matrix_sync(bf[j], &Ks[(warp_n * 32 + j * 16) * 64 + kk], 64);
#pragma unroll
                for (int j = 0; j < 2; j++)
                    wmma::mma_sync(sacc[j], af, bf[j], sacc[j]);
            }
#pragma unroll
            for (int j = 0; j < 2; j++)
                wmma::store_matrix_sync(&Ss[(warp_m * 16) * 64 + warp_n * 32 + j * 16],
                                        sacc[j], 64, wmma::mem_row_major);
        }
        __syncthreads();

        // P = exp(S*scale) with causal mask on diagonal tile; row sums
        {
            const bool diag = (kt == qt);
            float rs = 0.0f;
#pragma unroll
            for (int cc0 = 0; cc0 < 16; cc0++) {
                int cc = cg * 16 + cc0;
                float p;
                if (diag && cc > row) {
                    p = 0.0f;
                } else {
                    p = __expf(Ss[row * 64 + cc] * 0.125f);
                }
                rs += p;
                Ss[row * 64 + cc] = tf32c(p);
            }
            rs += __shfl_xor_sync(0xffffffffu, rs, 1);
            rs += __shfl_xor_sync(0xffffffffu, rs, 2);
            if (cg == 0) lrow[row] += rs;
        }
        __syncthreads();

        // O += P . V
#pragma unroll
        for (int kk = 0; kk < 64; kk += 8) {
            wmma::fragment<wmma::matrix_a, 16, 16, 8, wmma::precision::tf32, wmma::row_major> af;
            wmma::fragment<wmma::matrix_b, 16, 16, 8, wmma::precision::tf32, wmma::row_major> bf[2];
            wmma::load_matrix_sync(af, &Ss[(warp_m * 16) * 64 + kk], 64);
#pragma unroll
            for (int j = 0; j < 2; j++)
                wmma::load_matrix_sync(bf[j], &Vs[kk * 64 + warp_n * 32 + j * 16], 64);
#pragma unroll
            for (int j = 0; j < 2; j++)
                wmma::mma_sync(oacc[j], af, bf[j], oacc[j]);
        }
    }

    // dump partial O (unnormalized) + partial l for this chunk
    __syncthreads();
#pragma unroll
    for (int j = 0; j < 2; j++)
        wmma::store_matrix_sync(&Ss[(warp_m * 16) * 64 + warp_n * 32 + j * 16],
                                oacc[j], 64, wmma::mem_row_major);
    __syncthreads();
#pragma unroll
    for (int cc0 = 0; cc0 < 4; cc0++) {
        int cc = cg * 16 + cc0 * 4;
        *(float4*)&g_opart[c][(q0 + row) * DIM + h * HD + cc] =
            *(const float4*)&Ss[row * 64 + cc];
    }
    if (tid < 64) g_lpart[c][h * T + q0 + tid] = lrow[tid];
}

// ---------------------------------------------------------------------------
// Reduce: sum the active chunks' partial O / l per row, normalize -> g_att.
// Chunks beyond the causal range were never written; nch(qt) = qt/8 + 1.
// ---------------------------------------------------------------------------
__global__ void attn_reduce_kernel() {
    const int idx = blockIdx.x * blockDim.x + threadIdx.x;  // over T*DIM/4
    const int t = idx / (DIM / 4);
    const int d = (idx % (DIM / 4)) * 4;
    const int h = d / HD;
    const int nch = (t >> 6 >> 3) + 1;  // qt = t/64, nch = qt/8 + 1

    float4 o = make_float4(0.f, 0.f, 0.f, 0.f);
    float l = 0.f;
    for (int c = 0; c < nch; c++) {
        float4 p = *(const float4*)&g_opart[c][t * DIM + d];
        o.x += p.x; o.y += p.y; o.z += p.z; o.w += p.w;
        l += g_lpart[c][h * T + t];
    }
    float inv = 1.0f / l;
    o.x *= inv; o.y *= inv; o.z *= inv; o.w *= inv;
    *(float4*)&g_att[t * DIM + d] = o;
}

// ---------------------------------------------------------------------------
extern "C" void kernel_launch(void* const* d_in, const int* in_sizes, int n_in,
                              void* d_out, int out_size) {
    const float* x    = (const float*)d_in[0];
    const float* vi   = (const float*)d_in[1];
    const float* Wq   = (const float*)d_in[2];
    const float* Wk   = (const float*)d_in[3];
    const float* Wv   = (const float*)d_in[4];
    const float* Wp   = (const float*)d_in[5];
    const float* lamb = (const float*)d_in[6];
    float* out = (float*)d_out;

    static bool attr_set = false;
    if (!attr_set) {
        cudaFuncSetAttribute(attn_kernel,
                             cudaFuncAttributeMaxDynamicSharedMemorySize,
                             4 * 4096 * sizeof(float));
        attr_set = true;
    }

    dim3 gqkv(DIM / BN, T / BM, 3);
    gemm_qkv_kernel<<<gqkv, 256>>>(x, Wq, Wk, Wv);

    qkv_epilogue_kernel<<<(T * NH * 32) / 256, 256>>>(vi, lamb);

    dim3 gattn(T / 64, NH, NCHUNK);
    attn_kernel<<<gattn, 256, 4 * 4096 * sizeof(float)>>>();

    attn_reduce_kernel<<<(T * DIM / 4) / 256, 256>>>();

    dim3 gout(DIM / BN, T / BM, 1);
    gemm_out_kernel<<<gout, 256>>>(Wp, out);
}